// round 3
// baseline (speedup 1.0000x reference)
#include <cuda_runtime.h>
#include <math.h>

#define Bn 256
#define Tn 512
#define Fn 16
#define Hn 256
#define Gn (4*Hn)   // 1024

// ---- scratch (__device__ globals; no allocation allowed) ----
__device__ float g_Wc0[(Fn+Hn)*Gn];   // [272][1024] combined transposed weights, layer 0
__device__ float g_Wc1[(Hn+Hn)*Gn];   // [512][1024] layer 1
__device__ float g_b0[Gn], g_b1[Gn];  // combined biases (b_ih + b_hh)
__device__ float g_h0out[(size_t)Bn*Tn*Hn];  // layer-0 hidden sequence [b][t][u]
__device__ float g_hlast[Bn*Hn];             // layer-1 h at t = len-1

// ---------------- packed f32x2 helpers ----------------
__device__ __forceinline__ unsigned long long pack2(float a, float b) {
    unsigned long long r;
    asm("mov.b64 %0, {%1, %2};" : "=l"(r) : "f"(a), "f"(b));
    return r;
}
__device__ __forceinline__ void unpack2(unsigned long long v, float& a, float& b) {
    asm("mov.b64 {%0, %1}, %2;" : "=f"(a), "=f"(b) : "l"(v));
}
__device__ __forceinline__ void ffma2(unsigned long long& acc, unsigned long long a,
                                      unsigned long long b) {
    asm("fma.rn.f32x2 %0, %1, %2, %0;" : "+l"(acc) : "l"(a), "l"(b));
}

__device__ __forceinline__ float fast_sigmoid(float x) {
    return 1.f / (1.f + __expf(-x));
}

// ---------------- weight prep: transpose + combine ----------------
__global__ void prep_kernel(const float* __restrict__ wih0, const float* __restrict__ whh0,
                            const float* __restrict__ bih0, const float* __restrict__ bhh0,
                            const float* __restrict__ wih1, const float* __restrict__ whh1,
                            const float* __restrict__ bih1, const float* __restrict__ bhh1) {
    int idx = blockIdx.x * blockDim.x + threadIdx.x;
    int stride = gridDim.x * blockDim.x;
    const int n0 = (Fn+Hn)*Gn;
    const int n1 = (Hn+Hn)*Gn;
    for (int i = idx; i < n0; i += stride) {
        int k = i >> 10, j = i & (Gn-1);
        g_Wc0[i] = (k < Fn) ? wih0[j*Fn + k] : whh0[j*Hn + (k - Fn)];
    }
    for (int i = idx; i < n1; i += stride) {
        int k = i >> 10, j = i & (Gn-1);
        g_Wc1[i] = (k < Hn) ? wih1[j*Hn + k] : whh1[j*Hn + (k - Hn)];
    }
    for (int i = idx; i < Gn; i += stride) {
        g_b0[i] = bih0[i] + bhh0[i];
        g_b1[i] = bih1[i] + bhh1[i];
    }
}

// ---------------- persistent per-layer LSTM kernel ----------------
// One CTA owns 4 batch elements for the entire T=512 sequence.
// Thread j in [0,1024) computes gate row j for all 4 batches (f32x2 packed).
// Update phase: thread j -> (b = j>>8, u = j&255); c kept in a register.
template<int KIN, int XDIM, int LAYER>
__global__ __launch_bounds__(1024, 1)
void lstm_layer(const float* __restrict__ xin_ext, const int* __restrict__ lengths)
{
    __shared__ __align__(16) float v_sh[KIN][4];  // [k][b] : concat(x_t, h_prev)
    __shared__ float g_sh[4][Gn];                  // gate preactivations
    __shared__ int len_sh[4];

    const float* __restrict__ xin  = (LAYER == 0) ? xin_ext : g_h0out;
    const float* __restrict__ Wc   = (LAYER == 0) ? g_Wc0 : g_Wc1;
    const float* __restrict__ bias = (LAYER == 0) ? g_b0 : g_b1;

    const int j  = threadIdx.x;
    const int b0 = blockIdx.x * 4;
    const int bb = j >> 8;     // batch within tile (update phase)
    const int u  = j & 255;    // hidden unit (update phase)

    // zero h region of v, load lengths
    for (int i = j; i < KIN*4; i += 1024) ((float*)v_sh)[i] = 0.f;
    if (j < 4) len_sh[j] = lengths[b0 + j];

    float c_reg = 0.f;
    const float bj = bias[j];
    const unsigned long long bias2 = pack2(bj, bj);

    const float* wp = Wc + j;                 // invariant: column j base
    const float* xp_u = (XDIM == Hn) ? (xin + (size_t)(b0 + bb) * Tn * Hn + u) : xin;
    float* hout_p = (LAYER == 0)
        ? (g_h0out + (size_t)(b0 + bb) * Tn * Hn + u) : g_hlast;
    __syncthreads();

    for (int t = 0; t < Tn; ++t) {
        // ---- load x_t into v_sh[0..XDIM) ----
        if (XDIM == Fn) {
            if (j < 64) {
                int b = j >> 4, k = j & 15;
                v_sh[k][b] = xin_ext[((size_t)(b0 + b) * Tn + t) * Fn + k];
            }
        } else {
            v_sh[u][bb] = xp_u[(size_t)t * Hn];
        }
        __syncthreads();

        // ---- gates: acc = bias + Wc^T . v  (packed over batch pairs) ----
        unsigned long long acc01 = bias2, acc23 = bias2;
        #pragma unroll 8
        for (int k = 0; k < KIN; ++k) {
            float w = __ldg(wp + (size_t)k * Gn);
            ulonglong2 vv = *reinterpret_cast<const ulonglong2*>(&v_sh[k][0]);
            unsigned long long ww = pack2(w, w);
            ffma2(acc01, ww, vv.x);
            ffma2(acc23, ww, vv.y);
        }
        float a0, a1, a2, a3;
        unpack2(acc01, a0, a1);
        unpack2(acc23, a2, a3);
        g_sh[0][j] = a0; g_sh[1][j] = a1; g_sh[2][j] = a2; g_sh[3][j] = a3;
        __syncthreads();

        // ---- cell/hidden update (PyTorch gate order i,f,g,o) ----
        {
            float ig = g_sh[bb][u];
            float fg = g_sh[bb][256 + u];
            float gg = g_sh[bb][512 + u];
            float og = g_sh[bb][768 + u];
            float is = fast_sigmoid(ig);
            float fs = fast_sigmoid(fg);
            float os = fast_sigmoid(og);
            float gt = tanhf(gg);
            c_reg = fs * c_reg + is * gt;
            float h = os * tanhf(c_reg);
            v_sh[XDIM + u][bb] = h;   // next step's recurrent input
            if (LAYER == 0) {
                hout_p[(size_t)t * Hn] = h;
            } else {
                if (t == len_sh[bb] - 1) g_hlast[(b0 + bb) * Hn + u] = h;
            }
        }
        __syncthreads();
    }
}

// ---------------- final: relu(hlast) @ fc_w^T + fc_b ----------------
__global__ void final_kernel(const float* __restrict__ fc_w, const float* __restrict__ fc_b,
                             float* __restrict__ out) {
    __shared__ float red[256];
    int b = blockIdx.x, u = threadIdx.x;
    float v = fmaxf(g_hlast[b * Hn + u], 0.f) * fc_w[u];
    red[u] = v;
    __syncthreads();
    #pragma unroll
    for (int s = 128; s > 0; s >>= 1) {
        if (u < s) red[u] += red[u + s];
        __syncthreads();
    }
    if (u == 0) out[b] = red[0] + fc_b[0];
}

extern "C" void kernel_launch(void* const* d_in, const int* in_sizes, int n_in,
                              void* d_out, int out_size) {
    const float* x    = (const float*)d_in[0];
    const int*   lens = (const int*)  d_in[1];
    const float* wih0 = (const float*)d_in[2];
    const float* whh0 = (const float*)d_in[3];
    const float* bih0 = (const float*)d_in[4];
    const float* bhh0 = (const float*)d_in[5];
    const float* wih1 = (const float*)d_in[6];
    const float* whh1 = (const float*)d_in[7];
    const float* bih1 = (const float*)d_in[8];
    const float* bhh1 = (const float*)d_in[9];
    const float* fcw  = (const float*)d_in[10];
    const float* fcb  = (const float*)d_in[11];
    float* out = (float*)d_out;

    prep_kernel<<<148, 256>>>(wih0, whh0, bih0, bhh0, wih1, whh1, bih1, bhh1);
    lstm_layer<Fn + Hn, Fn, 0><<<Bn / 4, 1024>>>(x, lens);
    lstm_layer<Hn + Hn, Hn, 1><<<Bn / 4, 1024>>>(nullptr, lens);
    final_kernel<<<Bn, 256>>>(fcw, fcb, out);
}